// round 2
// baseline (speedup 1.0000x reference)
#include <cuda_runtime.h>
#include <cuda_bf16.h>

// GNN-VAE forward on GB300.
// Stages: CSR build (hist/scan/fill) -> GEMM1 -> gather-agg(64)+ReLU ->
//         fused per-node FCs (z, pred, hd) -> GEMM2 -> gather-agg(256).
// All scratch in __device__ globals (no allocations; graph-capturable).

#define NN 50000
#define EE 800000
#define F_IN 256
#define F_H  64
#define F_L  32

// ---------------- scratch (static device globals) ----------------
__device__ int   g_cnt[NN];
__device__ int   g_fill[NN];
__device__ int   g_rowptr[NN + 1];
__device__ int   g_col[EE];
__device__ float g_dinv[NN];
__device__ float g_hpre1[NN * F_H];   // x @ W_enc_gnn
__device__ float g_h1[NN * F_H];      // relu(gcn_enc)
__device__ float g_hd[NN * F_H];      // relu(z @ W_dec_fc + b)
__device__ float g_h2[NN * F_IN];     // hd @ W_dec_gnn

// ---------------- CSR build ----------------
__global__ void k_zero(int n) {
    int i = blockIdx.x * blockDim.x + threadIdx.x;
    if (i < n) { g_cnt[i] = 0; g_fill[i] = 0; }
}

__global__ void k_count(const int* __restrict__ dst, int e) {
    int i = blockIdx.x * blockDim.x + threadIdx.x;
    if (i < e) atomicAdd(&g_cnt[dst[i]], 1);
}

// Single block, 1024 threads: exclusive scan of g_cnt -> g_rowptr,
// plus dinv[i] = rsqrt(deg_i + 1)  (self loop included).
__global__ void k_scan(int n) {
    __shared__ int s[1024];
    __shared__ int base_s;
    int tid = threadIdx.x;
    if (tid == 0) base_s = 0;
    __syncthreads();
    for (int start = 0; start < n; start += 1024) {
        int i = start + tid;
        int v = (i < n) ? g_cnt[i] : 0;
        if (i < n) g_dinv[i] = rsqrtf((float)(v + 1));
        s[tid] = v;
        __syncthreads();
        #pragma unroll
        for (int off = 1; off < 1024; off <<= 1) {
            int t = (tid >= off) ? s[tid - off] : 0;
            __syncthreads();
            s[tid] += t;
            __syncthreads();
        }
        int incl = s[tid];
        int base = base_s;
        if (i < n) g_rowptr[i] = base + incl - v;   // exclusive
        __syncthreads();
        if (tid == 0) base_s = base + s[1023];
        __syncthreads();
    }
    if (tid == 0) g_rowptr[n] = base_s;
}

__global__ void k_fillcsr(const int* __restrict__ src, const int* __restrict__ dst, int e) {
    int i = blockIdx.x * blockDim.x + threadIdx.x;
    if (i < e) {
        int d = dst[i];
        int p = g_rowptr[d] + atomicAdd(&g_fill[d], 1);
        g_col[p] = src[i];
    }
}

// ---------------- fp32 tiled GEMM: C[M,N] = A[M,K] @ B[K,N] ----------------
// 64x64 tile per block, 256 threads, 4x4 per thread, BK=32.
// Requires K % 32 == 0, N % 64 == 0.
__global__ void k_gemm(const float* __restrict__ A, const float* __restrict__ B,
                       float* __restrict__ C, int M, int K, int N) {
    __shared__ float As[64 * 33];
    __shared__ alignas(16) float Bs[32 * 64];
    int tid = threadIdx.x;
    int ty = tid >> 4;          // 0..15
    int tx = tid & 15;          // 0..15
    int rowBase = blockIdx.y * 64;
    int colBase = blockIdx.x * 64;

    float acc[4][4];
    #pragma unroll
    for (int i = 0; i < 4; i++)
        #pragma unroll
        for (int j = 0; j < 4; j++) acc[i][j] = 0.f;

    for (int k0 = 0; k0 < K; k0 += 32) {
        #pragma unroll
        for (int l = 0; l < 8; l++) {
            int e = tid + l * 256;
            int r = e >> 5, kk = e & 31;
            int row = rowBase + r;
            As[r * 33 + kk] = (row < M) ? A[(size_t)row * K + k0 + kk] : 0.f;
        }
        #pragma unroll
        for (int l = 0; l < 8; l++) {
            int e = tid + l * 256;
            int kk = e >> 6, c = e & 63;
            Bs[kk * 64 + c] = B[(size_t)(k0 + kk) * N + colBase + c];
        }
        __syncthreads();
        #pragma unroll
        for (int kk = 0; kk < 32; kk++) {
            float4 b = *(const float4*)&Bs[kk * 64 + tx * 4];
            float a0 = As[(ty * 4 + 0) * 33 + kk];
            float a1 = As[(ty * 4 + 1) * 33 + kk];
            float a2 = As[(ty * 4 + 2) * 33 + kk];
            float a3 = As[(ty * 4 + 3) * 33 + kk];
            acc[0][0] += a0 * b.x; acc[0][1] += a0 * b.y; acc[0][2] += a0 * b.z; acc[0][3] += a0 * b.w;
            acc[1][0] += a1 * b.x; acc[1][1] += a1 * b.y; acc[1][2] += a1 * b.z; acc[1][3] += a1 * b.w;
            acc[2][0] += a2 * b.x; acc[2][1] += a2 * b.y; acc[2][2] += a2 * b.z; acc[2][3] += a2 * b.w;
            acc[3][0] += a3 * b.x; acc[3][1] += a3 * b.y; acc[3][2] += a3 * b.z; acc[3][3] += a3 * b.w;
        }
        __syncthreads();
    }
    #pragma unroll
    for (int i = 0; i < 4; i++) {
        int row = rowBase + ty * 4 + i;
        if (row < M) {
            float4 v = make_float4(acc[i][0], acc[i][1], acc[i][2], acc[i][3]);
            *(float4*)&C[(size_t)row * N + colBase + tx * 4] = v;
        }
    }
}

// ---------------- encoder aggregation (F=64) + bias + ReLU ----------------
// block per node, 64 threads = features.
// out[d] = relu( dinv[d] * ( sum_s dinv[s]*h[s] + dinv[d]*h[d] ) + b )
__global__ void k_agg_enc(const float* __restrict__ bias, int n) {
    int d = blockIdx.x;
    if (d >= n) return;
    int t = threadIdx.x;
    int beg = g_rowptr[d], end = g_rowptr[d + 1];
    float dd = g_dinv[d];
    float acc = dd * g_hpre1[(size_t)d * F_H + t];
    for (int p = beg; p < end; p++) {
        int s = g_col[p];
        acc += g_dinv[s] * g_hpre1[(size_t)s * F_H + t];
    }
    float out = dd * acc + bias[t];
    g_h1[(size_t)d * F_H + t] = fmaxf(out, 0.f);
}

// ---------------- fused per-node FCs: z, pred, hd ----------------
// warp per node: z[32] = h1[64]@Wef + b;  pred[3] = z@Wc + b;  hd[64] = relu(z@Wdf + b)
__global__ void k_fc(const float* __restrict__ Wef, const float* __restrict__ bef,
                     const float* __restrict__ Wdf, const float* __restrict__ bdf,
                     const float* __restrict__ Wc,  const float* __restrict__ bc,
                     float* __restrict__ out_z, float* __restrict__ out_pred, int n) {
    int warp = (blockIdx.x * blockDim.x + threadIdx.x) >> 5;
    int lane = threadIdx.x & 31;
    if (warp >= n) return;
    const unsigned FULL = 0xffffffffu;

    float h0 = g_h1[(size_t)warp * F_H + lane];
    float h1v = g_h1[(size_t)warp * F_H + 32 + lane];

    // z[lane]
    float z = bef[lane];
    #pragma unroll
    for (int k = 0; k < 32; k++)
        z += __shfl_sync(FULL, h0, k) * Wef[k * F_L + lane];
    #pragma unroll
    for (int k = 0; k < 32; k++)
        z += __shfl_sync(FULL, h1v, k) * Wef[(k + 32) * F_L + lane];
    out_z[(size_t)warp * F_L + lane] = z;

    // pred[3]
    #pragma unroll
    for (int o = 0; o < 3; o++) {
        float p = z * Wc[lane * 3 + o];
        #pragma unroll
        for (int off = 16; off > 0; off >>= 1)
            p += __shfl_xor_sync(FULL, p, off);
        if (lane == 0) out_pred[(size_t)warp * 3 + o] = p + bc[o];
    }

    // hd[64]
    float hd0 = bdf[lane], hd1 = bdf[lane + 32];
    #pragma unroll
    for (int j = 0; j < 32; j++) {
        float zj = __shfl_sync(FULL, z, j);
        hd0 += zj * Wdf[j * F_H + lane];
        hd1 += zj * Wdf[j * F_H + 32 + lane];
    }
    g_hd[(size_t)warp * F_H + lane]      = fmaxf(hd0, 0.f);
    g_hd[(size_t)warp * F_H + 32 + lane] = fmaxf(hd1, 0.f);
}

// ---------------- decoder aggregation (F=256) + bias ----------------
__global__ void k_agg_dec(const float* __restrict__ bias, float* __restrict__ xrec, int n) {
    int d = blockIdx.x;
    if (d >= n) return;
    int t = threadIdx.x;
    int beg = g_rowptr[d], end = g_rowptr[d + 1];
    float dd = g_dinv[d];
    float acc = dd * g_h2[(size_t)d * F_IN + t];
    for (int p = beg; p < end; p++) {
        int s = g_col[p];
        acc += g_dinv[s] * g_h2[(size_t)s * F_IN + t];
    }
    xrec[(size_t)d * F_IN + t] = dd * acc + bias[t];
}

// ---------------- launch ----------------
extern "C" void kernel_launch(void* const* d_in, const int* in_sizes, int n_in,
                              void* d_out, int out_size) {
    const float* x      = (const float*)d_in[0];
    const int*   ei     = (const int*)d_in[1];
    const float* W_enc  = (const float*)d_in[3];
    const float* b_enc  = (const float*)d_in[4];
    const float* Wef    = (const float*)d_in[5];
    const float* bef    = (const float*)d_in[6];
    const float* Wdf    = (const float*)d_in[7];
    const float* bdf    = (const float*)d_in[8];
    const float* W_dec  = (const float*)d_in[9];
    const float* b_dec  = (const float*)d_in[10];
    const float* Wc     = (const float*)d_in[11];
    const float* bc     = (const float*)d_in[12];

    int n = in_sizes[0] / F_IN;       // 50000
    int e = in_sizes[1] / 2;          // 800000
    const int* src = ei;
    const int* dst = ei + e;

    float* out_xrec = (float*)d_out;
    float* out_z    = out_xrec + (size_t)n * F_IN;
    float* out_pred = out_z + (size_t)n * F_L;

    // scratch as raw pointers (device symbols are directly addressable in
    // launches below via the globals themselves)
    float* hpre1 = nullptr; (void)hpre1;

    // 1) CSR build
    k_zero<<<(n + 255) / 256, 256>>>(n);
    k_count<<<(e + 255) / 256, 256>>>(dst, e);
    k_scan<<<1, 1024>>>(n);
    k_fillcsr<<<(e + 255) / 256, 256>>>(src, dst, e);

    // 2) GEMM1: hpre1 = x @ W_enc   [n,256]x[256,64]
    {
        float* C;  cudaGetSymbolAddress((void**)&C, g_hpre1);
        dim3 grid(1, (n + 63) / 64);
        k_gemm<<<grid, 256>>>(x, W_enc, C, n, F_IN, F_H);
    }

    // 3) encoder aggregation + relu
    k_agg_enc<<<n, F_H>>>(b_enc, n);

    // 4) fused FCs (z, pred, hd)
    {
        int warpsPerBlock = 8;
        int blocks = (n + warpsPerBlock - 1) / warpsPerBlock;
        k_fc<<<blocks, warpsPerBlock * 32>>>(Wef, bef, Wdf, bdf, Wc, bc,
                                             out_z, out_pred, n);
    }

    // 5) GEMM2: h2 = hd @ W_dec   [n,64]x[64,256]
    {
        float *A, *C;
        cudaGetSymbolAddress((void**)&A, g_hd);
        cudaGetSymbolAddress((void**)&C, g_h2);
        dim3 grid(F_IN / 64, (n + 63) / 64);
        k_gemm<<<grid, 256>>>(A, W_dec, C, n, F_H, F_IN);
    }

    // 6) decoder aggregation -> x_recon
    k_agg_dec<<<n, F_IN>>>(b_dec, out_xrec, n);

    (void)n_in; (void)out_size;
}

// round 4
// speedup vs baseline: 1.7377x; 1.7377x over previous
#include <cuda_runtime.h>
#include <cuda_fp16.h>

// GNN-VAE forward on GB300. R4 = R3 resubmit (infra failure last round):
// multi-block scan, fp16 aggregation sources, warp-per-node vectorized gathers.

#define NN 50000
#define EE 800000
#define F_IN 256
#define F_H  64
#define F_L  32
#define SCHUNK 512
#define NBLK_SCAN ((NN + SCHUNK - 1) / SCHUNK)   // 98

// ---------------- scratch (static device globals) ----------------
__device__ int    g_cnt[NN];
__device__ int    g_fill[NN];
__device__ int    g_rowptr[NN + 1];
__device__ int    g_col[EE];
__device__ float  g_dinv[NN];
__device__ int    g_bsum[NBLK_SCAN];
__device__ int    g_boff[NBLK_SCAN];
__device__ __half g_hpre1h[NN * F_H];   // x @ W_enc_gnn  (fp16 store)
__device__ float  g_h1[NN * F_H];       // relu(gcn_enc)
__device__ float  g_hd[NN * F_H];       // relu(z @ W_dec_fc + b)
__device__ __half g_h2h[NN * F_IN];     // hd @ W_dec_gnn (fp16 store)

// ---------------- CSR build ----------------
__global__ void k_zero(int n) {
    int i = blockIdx.x * blockDim.x + threadIdx.x;
    if (i < n) g_cnt[i] = 0;
}

__global__ void k_count(const int* __restrict__ dst, int e) {
    int i = blockIdx.x * blockDim.x + threadIdx.x;
    if (i < e) atomicAdd(&g_cnt[dst[i]], 1);
}

// pass 1: per-chunk exclusive scan + chunk totals + dinv
__global__ void k_scan1(int n) {
    __shared__ int s[SCHUNK];
    int tid = threadIdx.x;
    int i = blockIdx.x * SCHUNK + tid;
    int v = (i < n) ? g_cnt[i] : 0;
    if (i < n) g_dinv[i] = rsqrtf((float)(v + 1));
    s[tid] = v;
    __syncthreads();
    #pragma unroll
    for (int off = 1; off < SCHUNK; off <<= 1) {
        int t = (tid >= off) ? s[tid - off] : 0;
        __syncthreads();
        s[tid] += t;
        __syncthreads();
    }
    if (i < n) g_rowptr[i] = s[tid] - v;          // local exclusive
    if (tid == SCHUNK - 1) g_bsum[blockIdx.x] = s[SCHUNK - 1];
}

// pass 2: single small block scans the 98 chunk totals
__global__ void k_scan2(int nb) {
    __shared__ int s[128];
    int tid = threadIdx.x;
    int v = (tid < nb) ? g_bsum[tid] : 0;
    s[tid] = v;
    __syncthreads();
    #pragma unroll
    for (int off = 1; off < 128; off <<= 1) {
        int t = (tid >= off) ? s[tid - off] : 0;
        __syncthreads();
        s[tid] += t;
        __syncthreads();
    }
    if (tid < nb) g_boff[tid] = s[tid] - v;       // exclusive
}

// pass 3: add chunk offsets, zero fill cursors, close rowptr
__global__ void k_scan3(int n, int e) {
    int i = blockIdx.x * blockDim.x + threadIdx.x;
    if (i < n) {
        g_rowptr[i] += g_boff[i / SCHUNK];
        g_fill[i] = 0;
    }
    if (i == 0) g_rowptr[n] = e;
}

__global__ void k_fillcsr(const int* __restrict__ src, const int* __restrict__ dst, int e) {
    int i = blockIdx.x * blockDim.x + threadIdx.x;
    if (i < e) {
        int d = dst[i];
        int p = g_rowptr[d] + atomicAdd(&g_fill[d], 1);
        g_col[p] = src[i];
    }
}

// ---------------- fp32 tiled GEMM with fp16 output ----------------
// C[M,N](half) = A[M,K](fp32) @ B[K,N](fp32). 64x64 tile, 256 threads, 4x4/thread.
__global__ void __launch_bounds__(256)
k_gemm_h(const float* __restrict__ A, const float* __restrict__ B,
         __half* __restrict__ C, int M, int K, int N) {
    __shared__ float As[64 * 33];
    __shared__ alignas(16) float Bs[32 * 64];
    int tid = threadIdx.x;
    int ty = tid >> 4;
    int tx = tid & 15;
    int rowBase = blockIdx.y * 64;
    int colBase = blockIdx.x * 64;

    float acc[4][4];
    #pragma unroll
    for (int i = 0; i < 4; i++)
        #pragma unroll
        for (int j = 0; j < 4; j++) acc[i][j] = 0.f;

    for (int k0 = 0; k0 < K; k0 += 32) {
        #pragma unroll
        for (int l = 0; l < 8; l++) {
            int e = tid + l * 256;
            int r = e >> 5, kk = e & 31;
            int row = rowBase + r;
            As[r * 33 + kk] = (row < M) ? A[(size_t)row * K + k0 + kk] : 0.f;
        }
        #pragma unroll
        for (int l = 0; l < 8; l++) {
            int e = tid + l * 256;
            int kk = e >> 6, c = e & 63;
            Bs[kk * 64 + c] = B[(size_t)(k0 + kk) * N + colBase + c];
        }
        __syncthreads();
        #pragma unroll
        for (int kk = 0; kk < 32; kk++) {
            float4 b = *(const float4*)&Bs[kk * 64 + tx * 4];
            float a0 = As[(ty * 4 + 0) * 33 + kk];
            float a1 = As[(ty * 4 + 1) * 33 + kk];
            float a2 = As[(ty * 4 + 2) * 33 + kk];
            float a3 = As[(ty * 4 + 3) * 33 + kk];
            acc[0][0] += a0 * b.x; acc[0][1] += a0 * b.y; acc[0][2] += a0 * b.z; acc[0][3] += a0 * b.w;
            acc[1][0] += a1 * b.x; acc[1][1] += a1 * b.y; acc[1][2] += a1 * b.z; acc[1][3] += a1 * b.w;
            acc[2][0] += a2 * b.x; acc[2][1] += a2 * b.y; acc[2][2] += a2 * b.z; acc[2][3] += a2 * b.w;
            acc[3][0] += a3 * b.x; acc[3][1] += a3 * b.y; acc[3][2] += a3 * b.z; acc[3][3] += a3 * b.w;
        }
        __syncthreads();
    }
    #pragma unroll
    for (int i = 0; i < 4; i++) {
        int row = rowBase + ty * 4 + i;
        if (row < M) {
            __half2 p01 = __floats2half2_rn(acc[i][0], acc[i][1]);
            __half2 p23 = __floats2half2_rn(acc[i][2], acc[i][3]);
            uint2 st;
            st.x = *(unsigned int*)&p01;
            st.y = *(unsigned int*)&p23;
            *(uint2*)(C + (size_t)row * N + colBase + tx * 4) = st;
        }
    }
}

// ---------------- encoder aggregation (F=64, fp16 src) + bias + ReLU ------
// warp per node; lane owns one half2 (2 features).
__global__ void __launch_bounds__(256)
k_agg_enc(const float* __restrict__ bias, int n) {
    int warp = (blockIdx.x * blockDim.x + threadIdx.x) >> 5;
    int lane = threadIdx.x & 31;
    if (warp >= n) return;
    int d = warp;
    int beg = g_rowptr[d], end = g_rowptr[d + 1];
    float dd = g_dinv[d];
    const __half2* hp = (const __half2*)g_hpre1h;

    float2 sv = __half22float2(hp[(size_t)d * 32 + lane]);
    float ax = dd * sv.x, ay = dd * sv.y;

    int p = beg;
    for (; p + 4 <= end; p += 4) {
        int s0 = g_col[p], s1 = g_col[p + 1], s2 = g_col[p + 2], s3 = g_col[p + 3];
        float w0 = g_dinv[s0], w1 = g_dinv[s1], w2 = g_dinv[s2], w3 = g_dinv[s3];
        float2 v0 = __half22float2(hp[(size_t)s0 * 32 + lane]);
        float2 v1 = __half22float2(hp[(size_t)s1 * 32 + lane]);
        float2 v2 = __half22float2(hp[(size_t)s2 * 32 + lane]);
        float2 v3 = __half22float2(hp[(size_t)s3 * 32 + lane]);
        ax += w0 * v0.x + w1 * v1.x + w2 * v2.x + w3 * v3.x;
        ay += w0 * v0.y + w1 * v1.y + w2 * v2.y + w3 * v3.y;
    }
    for (; p < end; p++) {
        int s = g_col[p];
        float w = g_dinv[s];
        float2 v = __half22float2(hp[(size_t)s * 32 + lane]);
        ax += w * v.x;
        ay += w * v.y;
    }
    float2 b = ((const float2*)bias)[lane];
    float2 o;
    o.x = fmaxf(dd * ax + b.x, 0.f);
    o.y = fmaxf(dd * ay + b.y, 0.f);
    ((float2*)g_h1)[(size_t)d * 32 + lane] = o;
}

// ---------------- fused per-node FCs: z, pred, hd ----------------
__global__ void __launch_bounds__(256)
k_fc(const float* __restrict__ Wef, const float* __restrict__ bef,
     const float* __restrict__ Wdf, const float* __restrict__ bdf,
     const float* __restrict__ Wc,  const float* __restrict__ bc,
     float* __restrict__ out_z, float* __restrict__ out_pred, int n) {
    int warp = (blockIdx.x * blockDim.x + threadIdx.x) >> 5;
    int lane = threadIdx.x & 31;
    if (warp >= n) return;
    const unsigned FULL = 0xffffffffu;

    float h0 = g_h1[(size_t)warp * F_H + lane];
    float h1v = g_h1[(size_t)warp * F_H + 32 + lane];

    float z = bef[lane];
    #pragma unroll
    for (int k = 0; k < 32; k++)
        z += __shfl_sync(FULL, h0, k) * Wef[k * F_L + lane];
    #pragma unroll
    for (int k = 0; k < 32; k++)
        z += __shfl_sync(FULL, h1v, k) * Wef[(k + 32) * F_L + lane];
    out_z[(size_t)warp * F_L + lane] = z;

    #pragma unroll
    for (int o = 0; o < 3; o++) {
        float p = z * Wc[lane * 3 + o];
        #pragma unroll
        for (int off = 16; off > 0; off >>= 1)
            p += __shfl_xor_sync(FULL, p, off);
        if (lane == 0) out_pred[(size_t)warp * 3 + o] = p + bc[o];
    }

    float hd0 = bdf[lane], hd1 = bdf[lane + 32];
    #pragma unroll
    for (int j = 0; j < 32; j++) {
        float zj = __shfl_sync(FULL, z, j);
        hd0 += zj * Wdf[j * F_H + lane];
        hd1 += zj * Wdf[j * F_H + 32 + lane];
    }
    g_hd[(size_t)warp * F_H + lane]      = fmaxf(hd0, 0.f);
    g_hd[(size_t)warp * F_H + 32 + lane] = fmaxf(hd1, 0.f);
}

// ---------------- decoder aggregation (F=256, fp16 src) + bias ------------
// warp per node; lane owns 8 halves (one uint4 = 16B) of the 512B row.
__device__ __forceinline__ void acc8(float* a, uint4 v, float w) {
    float2 f0 = __half22float2(*(__half2*)&v.x);
    float2 f1 = __half22float2(*(__half2*)&v.y);
    float2 f2 = __half22float2(*(__half2*)&v.z);
    float2 f3 = __half22float2(*(__half2*)&v.w);
    a[0] += w * f0.x; a[1] += w * f0.y;
    a[2] += w * f1.x; a[3] += w * f1.y;
    a[4] += w * f2.x; a[5] += w * f2.y;
    a[6] += w * f3.x; a[7] += w * f3.y;
}

__global__ void __launch_bounds__(256)
k_agg_dec(const float* __restrict__ bias, float* __restrict__ xrec, int n) {
    int warp = (blockIdx.x * blockDim.x + threadIdx.x) >> 5;
    int lane = threadIdx.x & 31;
    if (warp >= n) return;
    int d = warp;
    int beg = g_rowptr[d], end = g_rowptr[d + 1];
    float dd = g_dinv[d];
    const uint4* h2 = (const uint4*)g_h2h;      // 32 uint4 per row

    float acc[8];
    uint4 sv = h2[(size_t)d * 32 + lane];
    #pragma unroll
    for (int k = 0; k < 8; k++) acc[k] = 0.f;
    acc8(acc, sv, dd);

    int p = beg;
    for (; p + 4 <= end; p += 4) {
        int s0 = g_col[p], s1 = g_col[p + 1], s2 = g_col[p + 2], s3 = g_col[p + 3];
        float w0 = g_dinv[s0], w1 = g_dinv[s1], w2 = g_dinv[s2], w3 = g_dinv[s3];
        uint4 v0 = h2[(size_t)s0 * 32 + lane];
        uint4 v1 = h2[(size_t)s1 * 32 + lane];
        uint4 v2 = h2[(size_t)s2 * 32 + lane];
        uint4 v3 = h2[(size_t)s3 * 32 + lane];
        acc8(acc, v0, w0);
        acc8(acc, v1, w1);
        acc8(acc, v2, w2);
        acc8(acc, v3, w3);
    }
    for (; p < end; p++) {
        int s = g_col[p];
        acc8(acc, h2[(size_t)s * 32 + lane], g_dinv[s]);
    }

    float4 b0 = ((const float4*)bias)[lane * 2];
    float4 b1 = ((const float4*)bias)[lane * 2 + 1];
    float* o = xrec + (size_t)d * F_IN + lane * 8;
    float4 r0 = make_float4(dd * acc[0] + b0.x, dd * acc[1] + b0.y,
                            dd * acc[2] + b0.z, dd * acc[3] + b0.w);
    float4 r1 = make_float4(dd * acc[4] + b1.x, dd * acc[5] + b1.y,
                            dd * acc[6] + b1.z, dd * acc[7] + b1.w);
    *(float4*)o = r0;
    *(float4*)(o + 4) = r1;
}

// ---------------- launch ----------------
extern "C" void kernel_launch(void* const* d_in, const int* in_sizes, int n_in,
                              void* d_out, int out_size) {
    const float* x      = (const float*)d_in[0];
    const int*   ei     = (const int*)d_in[1];
    const float* W_enc  = (const float*)d_in[3];
    const float* b_enc  = (const float*)d_in[4];
    const float* Wef    = (const float*)d_in[5];
    const float* bef    = (const float*)d_in[6];
    const float* Wdf    = (const float*)d_in[7];
    const float* bdf    = (const float*)d_in[8];
    const float* W_dec  = (const float*)d_in[9];
    const float* b_dec  = (const float*)d_in[10];
    const float* Wc     = (const float*)d_in[11];
    const float* bc     = (const float*)d_in[12];

    int n = in_sizes[0] / F_IN;       // 50000
    int e = in_sizes[1] / 2;          // 800000
    const int* src = ei;
    const int* dst = ei + e;

    float* out_xrec = (float*)d_out;
    float* out_z    = out_xrec + (size_t)n * F_IN;
    float* out_pred = out_z + (size_t)n * F_L;

    // 1) CSR build
    k_zero<<<(n + 255) / 256, 256>>>(n);
    k_count<<<(e + 255) / 256, 256>>>(dst, e);
    int nb = (n + SCHUNK - 1) / SCHUNK;
    k_scan1<<<nb, SCHUNK>>>(n);
    k_scan2<<<1, 128>>>(nb);
    k_scan3<<<(n + 255) / 256, 256>>>(n, e);
    k_fillcsr<<<(e + 255) / 256, 256>>>(src, dst, e);

    // 2) GEMM1: hpre1h = x @ W_enc  [n,256]x[256,64] -> half
    {
        __half* C;  cudaGetSymbolAddress((void**)&C, g_hpre1h);
        dim3 grid(1, (n + 63) / 64);
        k_gemm_h<<<grid, 256>>>(x, W_enc, C, n, F_IN, F_H);
    }

    // 3) encoder aggregation + relu (warp per node)
    {
        int blocks = (int)(((size_t)n * 32 + 255) / 256);
        k_agg_enc<<<blocks, 256>>>(b_enc, n);
    }

    // 4) fused FCs (z, pred, hd)
    {
        int blocks = (n + 7) / 8;
        k_fc<<<blocks, 256>>>(Wef, bef, Wdf, bdf, Wc, bc, out_z, out_pred, n);
    }

    // 5) GEMM2: h2h = hd @ W_dec  [n,64]x[64,256] -> half
    {
        float* A; __half* C;
        cudaGetSymbolAddress((void**)&A, g_hd);
        cudaGetSymbolAddress((void**)&C, g_h2h);
        dim3 grid(F_IN / 64, (n + 63) / 64);
        k_gemm_h<<<grid, 256>>>(A, W_dec, C, n, F_H, F_IN);
    }

    // 6) decoder aggregation -> x_recon (warp per node)
    {
        int blocks = (int)(((size_t)n * 32 + 255) / 256);
        k_agg_dec<<<blocks, 256>>>(b_dec, out_xrec, n);
    }

    (void)n_in; (void)out_size;
}

// round 7
// speedup vs baseline: 2.3122x; 1.3307x over previous
#include <cuda_runtime.h>
#include <cuda_fp16.h>
#include <cstdint>

// GNN-VAE forward on GB300. R5: tensor-core (HMMA m16n8k16) GEMMs replace
// SIMT fp32 GEMMs; everything else identical to R4 for clean attribution.

#define NN 50000
#define EE 800000
#define F_IN 256
#define F_H  64
#define F_L  32
#define SCHUNK 512
#define NBLK_SCAN ((NN + SCHUNK - 1) / SCHUNK)   // 98

// ---------------- scratch (static device globals) ----------------
__device__ int    g_cnt[NN];
__device__ int    g_fill[NN];
__device__ int    g_rowptr[NN + 1];
__device__ int    g_col[EE];
__device__ float  g_dinv[NN];
__device__ int    g_bsum[NBLK_SCAN];
__device__ int    g_boff[NBLK_SCAN];
__device__ __half g_hpre1h[NN * F_H];   // x @ W_enc_gnn  (fp16)
__device__ float  g_h1[NN * F_H];       // relu(gcn_enc)
__device__ __half g_hdh[NN * F_H];      // relu(z @ W_dec_fc + b)  (fp16)
__device__ __half g_h2h[NN * F_IN];     // hd @ W_dec_gnn (fp16)

// ---------------- CSR build ----------------
__global__ void k_zero(int n) {
    int i = blockIdx.x * blockDim.x + threadIdx.x;
    if (i < n) g_cnt[i] = 0;
}

__global__ void k_count(const int* __restrict__ dst, int e) {
    int i = blockIdx.x * blockDim.x + threadIdx.x;
    if (i < e) atomicAdd(&g_cnt[dst[i]], 1);
}

__global__ void k_scan1(int n) {
    __shared__ int s[SCHUNK];
    int tid = threadIdx.x;
    int i = blockIdx.x * SCHUNK + tid;
    int v = (i < n) ? g_cnt[i] : 0;
    if (i < n) g_dinv[i] = rsqrtf((float)(v + 1));
    s[tid] = v;
    __syncthreads();
    #pragma unroll
    for (int off = 1; off < SCHUNK; off <<= 1) {
        int t = (tid >= off) ? s[tid - off] : 0;
        __syncthreads();
        s[tid] += t;
        __syncthreads();
    }
    if (i < n) g_rowptr[i] = s[tid] - v;
    if (tid == SCHUNK - 1) g_bsum[blockIdx.x] = s[SCHUNK - 1];
}

__global__ void k_scan2(int nb) {
    __shared__ int s[128];
    int tid = threadIdx.x;
    int v = (tid < nb) ? g_bsum[tid] : 0;
    s[tid] = v;
    __syncthreads();
    #pragma unroll
    for (int off = 1; off < 128; off <<= 1) {
        int t = (tid >= off) ? s[tid - off] : 0;
        __syncthreads();
        s[tid] += t;
        __syncthreads();
    }
    if (tid < nb) g_boff[tid] = s[tid] - v;
}

__global__ void k_scan3(int n, int e) {
    int i = blockIdx.x * blockDim.x + threadIdx.x;
    if (i < n) {
        g_rowptr[i] += g_boff[i / SCHUNK];
        g_fill[i] = 0;
    }
    if (i == 0) g_rowptr[n] = e;
}

__global__ void k_fillcsr(const int* __restrict__ src, const int* __restrict__ dst, int e) {
    int i = blockIdx.x * blockDim.x + threadIdx.x;
    if (i < e) {
        int d = dst[i];
        int p = g_rowptr[d] + atomicAdd(&g_fill[d], 1);
        g_col[p] = src[i];
    }
}

// ---------------- HMMA GEMM: C[M,N](half) = A[M,K] @ B[K,N](fp32) ---------
// Block tile 64x64, BK=32, 128 threads (4 warps, each 32x32).
// A is fp32 (A_HALF=false) or fp16 (A_HALF=true); converted to fp16 in smem.
// Requires K%32==0, N%64==0 (holds: K in {256,64}, N in {64,256}).

__device__ __forceinline__ void ldmat_x4(uint32_t& r0, uint32_t& r1,
                                         uint32_t& r2, uint32_t& r3, uint32_t addr) {
    asm volatile("ldmatrix.sync.aligned.m8n8.x4.shared.b16 {%0,%1,%2,%3}, [%4];"
                 : "=r"(r0), "=r"(r1), "=r"(r2), "=r"(r3) : "r"(addr));
}
__device__ __forceinline__ void ldmat_x4t(uint32_t& r0, uint32_t& r1,
                                          uint32_t& r2, uint32_t& r3, uint32_t addr) {
    asm volatile("ldmatrix.sync.aligned.m8n8.x4.trans.shared.b16 {%0,%1,%2,%3}, [%4];"
                 : "=r"(r0), "=r"(r1), "=r"(r2), "=r"(r3) : "r"(addr));
}
__device__ __forceinline__ void mma16816(float* d, const uint32_t* a,
                                         uint32_t b0, uint32_t b1) {
    asm volatile("mma.sync.aligned.m16n8k16.row.col.f32.f16.f16.f32 "
                 "{%0,%1,%2,%3}, {%4,%5,%6,%7}, {%8,%9}, {%0,%1,%2,%3};"
                 : "+f"(d[0]), "+f"(d[1]), "+f"(d[2]), "+f"(d[3])
                 : "r"(a[0]), "r"(a[1]), "r"(a[2]), "r"(a[3]), "r"(b0), "r"(b1));
}

template <bool A_HALF>
__global__ void __launch_bounds__(128)
k_gemm_mma(const void* __restrict__ Aptr, const float* __restrict__ B,
           __half* __restrict__ C, int M, int K, int N) {
    constexpr int BM = 64, BN = 64, BK = 32;
    constexpr int ASTR = BK + 8;   // 40 halves = 80B row stride (16B aligned)
    constexpr int BSTR = BN + 8;   // 72 halves = 144B row stride (16B aligned)
    __shared__ __half As[BM * ASTR];
    __shared__ __half Bs[BK * BSTR];

    int tid = threadIdx.x;
    int wid = tid >> 5, lane = tid & 31;
    int wm = (wid >> 1) * 32;          // warp row offset in tile
    int wn = (wid & 1) * 32;           // warp col offset in tile
    int rowBase = blockIdx.y * BM;
    int colBase = blockIdx.x * BN;

    float acc[2][4][4];
    #pragma unroll
    for (int i = 0; i < 2; i++)
        #pragma unroll
        for (int j = 0; j < 4; j++)
            #pragma unroll
            for (int k = 0; k < 4; k++) acc[i][j][k] = 0.f;

    for (int k0 = 0; k0 < K; k0 += BK) {
        // ---- load A tile (64 x 32 halves); 256 16B units, 2 per thread ----
        #pragma unroll
        for (int u = tid; u < 256; u += 128) {
            int r = u >> 2, c = (u & 3) * 8;
            int grow = rowBase + r;
            uint4 v = make_uint4(0, 0, 0, 0);
            if (grow < M) {
                if (A_HALF) {
                    v = *(const uint4*)((const __half*)Aptr + (size_t)grow * K + k0 + c);
                } else {
                    const float* p = (const float*)Aptr + (size_t)grow * K + k0 + c;
                    float4 f0 = *(const float4*)p;
                    float4 f1 = *(const float4*)(p + 4);
                    __half2 h0 = __floats2half2_rn(f0.x, f0.y);
                    __half2 h1 = __floats2half2_rn(f0.z, f0.w);
                    __half2 h2 = __floats2half2_rn(f1.x, f1.y);
                    __half2 h3 = __floats2half2_rn(f1.z, f1.w);
                    v.x = *(uint32_t*)&h0; v.y = *(uint32_t*)&h1;
                    v.z = *(uint32_t*)&h2; v.w = *(uint32_t*)&h3;
                }
            }
            *(uint4*)&As[r * ASTR + c] = v;
        }
        // ---- load B tile (32 x 64 fp32 -> halves); 256 units ----
        #pragma unroll
        for (int u = tid; u < 256; u += 128) {
            int kk = u >> 3, c = (u & 7) * 8;
            const float* p = B + (size_t)(k0 + kk) * N + colBase + c;
            float4 f0 = *(const float4*)p;
            float4 f1 = *(const float4*)(p + 4);
            __half2 h0 = __floats2half2_rn(f0.x, f0.y);
            __half2 h1 = __floats2half2_rn(f0.z, f0.w);
            __half2 h2 = __floats2half2_rn(f1.x, f1.y);
            __half2 h3 = __floats2half2_rn(f1.z, f1.w);
            uint4 v;
            v.x = *(uint32_t*)&h0; v.y = *(uint32_t*)&h1;
            v.z = *(uint32_t*)&h2; v.w = *(uint32_t*)&h3;
            *(uint4*)&Bs[kk * BSTR + c] = v;
        }
        __syncthreads();

        // ---- compute: two k16 steps ----
        #pragma unroll
        for (int kk = 0; kk < BK; kk += 16) {
            uint32_t a[2][4];
            #pragma unroll
            for (int mi = 0; mi < 2; mi++) {
                const __half* p = &As[(wm + mi * 16 + (lane & 15)) * ASTR + kk + (lane >> 4) * 8];
                uint32_t addr = (uint32_t)__cvta_generic_to_shared(p);
                ldmat_x4(a[mi][0], a[mi][1], a[mi][2], a[mi][3], addr);
            }
            #pragma unroll
            for (int nj = 0; nj < 2; nj++) {
                uint32_t b0, b1, b2, b3;
                const __half* p = &Bs[(kk + (lane & 15)) * BSTR + wn + nj * 16 + (lane >> 4) * 8];
                uint32_t addr = (uint32_t)__cvta_generic_to_shared(p);
                ldmat_x4t(b0, b1, b2, b3, addr);
                #pragma unroll
                for (int mi = 0; mi < 2; mi++) {
                    mma16816(acc[mi][nj * 2 + 0], a[mi], b0, b1);
                    mma16816(acc[mi][nj * 2 + 1], a[mi], b2, b3);
                }
            }
        }
        __syncthreads();
    }

    // ---- epilogue: fp16 store ----
    int group = lane >> 2;            // 0..7
    int tig   = lane & 3;             // 0..3
    #pragma unroll
    for (int mi = 0; mi < 2; mi++) {
        #pragma unroll
        for (int nj = 0; nj < 4; nj++) {
            int col = colBase + wn + nj * 8 + tig * 2;
            int r0 = rowBase + wm + mi * 16 + group;
            int r1 = r0 + 8;
            __half2 h0 = __floats2half2_rn(acc[mi][nj][0], acc[mi][nj][1]);
            __half2 h1 = __floats2half2_rn(acc[mi][nj][2], acc[mi][nj][3]);
            if (r0 < M) *(__half2*)(C + (size_t)r0 * N + col) = h0;
            if (r1 < M) *(__half2*)(C + (size_t)r1 * N + col) = h1;
        }
    }
}

// ---------------- encoder aggregation (F=64, fp16 src) + bias + ReLU ------
__global__ void __launch_bounds__(256)
k_agg_enc(const float* __restrict__ bias, int n) {
    int warp = (blockIdx.x * blockDim.x + threadIdx.x) >> 5;
    int lane = threadIdx.x & 31;
    if (warp >= n) return;
    int d = warp;
    int beg = g_rowptr[d], end = g_rowptr[d + 1];
    float dd = g_dinv[d];
    const __half2* hp = (const __half2*)g_hpre1h;

    float2 sv = __half22float2(hp[(size_t)d * 32 + lane]);
    float ax = dd * sv.x, ay = dd * sv.y;

    int p = beg;
    for (; p + 4 <= end; p += 4) {
        int s0 = g_col[p], s1 = g_col[p + 1], s2 = g_col[p + 2], s3 = g_col[p + 3];
        float w0 = g_dinv[s0], w1 = g_dinv[s1], w2 = g_dinv[s2], w3 = g_dinv[s3];
        float2 v0 = __half22float2(hp[(size_t)s0 * 32 + lane]);
        float2 v1 = __half22float2(hp[(size_t)s1 * 32 + lane]);
        float2 v2 = __half22float2(hp[(size_t)s2 * 32 + lane]);
        float2 v3 = __half22float2(hp[(size_t)s3 * 32 + lane]);
        ax += w0 * v0.x + w1 * v1.x + w2 * v2.x + w3 * v3.x;
        ay += w0 * v0.y + w1 * v1.y + w2 * v2.y + w3 * v3.y;
    }
    for (; p < end; p++) {
        int s = g_col[p];
        float w = g_dinv[s];
        float2 v = __half22float2(hp[(size_t)s * 32 + lane]);
        ax += w * v.x;
        ay += w * v.y;
    }
    float2 b = ((const float2*)bias)[lane];
    float2 o;
    o.x = fmaxf(dd * ax + b.x, 0.f);
    o.y = fmaxf(dd * ay + b.y, 0.f);
    ((float2*)g_h1)[(size_t)d * 32 + lane] = o;
}

// ---------------- fused per-node FCs: z, pred, hd(fp16) ----------------
__global__ void __launch_bounds__(256)
k_fc(const float* __restrict__ Wef, const float* __restrict__ bef,
     const float* __restrict__ Wdf, const float* __restrict__ bdf,
     const float* __restrict__ Wc,  const float* __restrict__ bc,
     float* __restrict__ out_z, float* __restrict__ out_pred, int n) {
    int warp = (blockIdx.x * blockDim.x + threadIdx.x) >> 5;
    int lane = threadIdx.x & 31;
    if (warp >= n) return;
    const unsigned FULL = 0xffffffffu;

    float h0 = g_h1[(size_t)warp * F_H + lane];
    float h1v = g_h1[(size_t)warp * F_H + 32 + lane];

    float z = bef[lane];
    #pragma unroll
    for (int k = 0; k < 32; k++)
        z += __shfl_sync(FULL, h0, k) * Wef[k * F_L + lane];
    #pragma unroll
    for (int k = 0; k < 32; k++)
        z += __shfl_sync(FULL, h1v, k) * Wef[(k + 32) * F_L + lane];
    out_z[(size_t)warp * F_L + lane] = z;

    #pragma unroll
    for (int o = 0; o < 3; o++) {
        float p = z * Wc[lane * 3 + o];
        #pragma unroll
        for (int off = 16; off > 0; off >>= 1)
            p += __shfl_xor_sync(FULL, p, off);
        if (lane == 0) out_pred[(size_t)warp * 3 + o] = p + bc[o];
    }

    float hd0 = bdf[lane], hd1 = bdf[lane + 32];
    #pragma unroll
    for (int j = 0; j < 32; j++) {
        float zj = __shfl_sync(FULL, z, j);
        hd0 += zj * Wdf[j * F_H + lane];
        hd1 += zj * Wdf[j * F_H + 32 + lane];
    }
    __half2* hd = (__half2*)g_hdh;
    hd[(size_t)warp * 32 + (lane & 15) + ((lane >> 4) << 4)] =
        __floats2half2_rn(0.f, 0.f);  // placeholder overwritten below (keeps layout simple)
    // store as two scalar halves (simple, 6.4MB total traffic)
    g_hdh[(size_t)warp * F_H + lane]      = __float2half_rn(fmaxf(hd0, 0.f));
    g_hdh[(size_t)warp * F_H + 32 + lane] = __float2half_rn(fmaxf(hd1, 0.f));
}

// ---------------- decoder aggregation (F=256, fp16 src) + bias ------------
__device__ __forceinline__ void acc8(float* a, uint4 v, float w) {
    float2 f0 = __half22float2(*(__half2*)&v.x);
    float2 f1 = __half22float2(*(__half2*)&v.y);
    float2 f2 = __half22float2(*(__half2*)&v.z);
    float2 f3 = __half22float2(*(__half2*)&v.w);
    a[0] += w * f0.x; a[1] += w * f0.y;
    a[2] += w * f1.x; a[3] += w * f1.y;
    a[4] += w * f2.x; a[5] += w * f2.y;
    a[6] += w * f3.x; a[7] += w * f3.y;
}

__global__ void __launch_bounds__(256)
k_agg_dec(const float* __restrict__ bias, float* __restrict__ xrec, int n) {
    int warp = (blockIdx.x * blockDim.x + threadIdx.x) >> 5;
    int lane = threadIdx.x & 31;
    if (warp >= n) return;
    int d = warp;
    int beg = g_rowptr[d], end = g_rowptr[d + 1];
    float dd = g_dinv[d];
    const uint4* h2 = (const uint4*)g_h2h;

    float acc[8];
    uint4 sv = h2[(size_t)d * 32 + lane];
    #pragma unroll
    for (int k = 0; k < 8; k++) acc[k] = 0.f;
    acc8(acc, sv, dd);

    int p = beg;
    for (; p + 4 <= end; p += 4) {
        int s0 = g_col[p], s1 = g_col[p + 1], s2 = g_col[p + 2], s3 = g_col[p + 3];
        float w0 = g_dinv[s0], w1 = g_dinv[s1], w2 = g_dinv[s2], w3 = g_dinv[s3];
        uint4 v0 = h2[(size_t)s0 * 32 + lane];
        uint4 v1 = h2[(size_t)s1 * 32 + lane];
        uint4 v2 = h2[(size_t)s2 * 32 + lane];
        uint4 v3 = h2[(size_t)s3 * 32 + lane];
        acc8(acc, v0, w0);
        acc8(acc, v1, w1);
        acc8(acc, v2, w2);
        acc8(acc, v3, w3);
    }
    for (; p < end; p++) {
        int s = g_col[p];
        acc8(acc, h2[(size_t)s * 32 + lane], g_dinv[s]);
    }

    float4 b0 = ((const float4*)bias)[lane * 2];
    float4 b1 = ((const float4*)bias)[lane * 2 + 1];
    float* o = xrec + (size_t)d * F_IN + lane * 8;
    float4 r0 = make_float4(dd * acc[0] + b0.x, dd * acc[1] + b0.y,
                            dd * acc[2] + b0.z, dd * acc[3] + b0.w);
    float4 r1 = make_float4(dd * acc[4] + b1.x, dd * acc[5] + b1.y,
                            dd * acc[6] + b1.z, dd * acc[7] + b1.w);
    *(float4*)o = r0;
    *(float4*)(o + 4) = r1;
}

// ---------------- launch ----------------
extern "C" void kernel_launch(void* const* d_in, const int* in_sizes, int n_in,
                              void* d_out, int out_size) {
    const float* x      = (const float*)d_in[0];
    const int*   ei     = (const int*)d_in[1];
    const float* W_enc  = (const float*)d_in[3];
    const float* b_enc  = (const float*)d_in[4];
    const float* Wef    = (const float*)d_in[5];
    const float* bef    = (const float*)d_in[6];
    const float* Wdf    = (const float*)d_in[7];
    const float* bdf    = (const float*)d_in[8];
    const float* W_dec  = (const float*)d_in[9];
    const float* b_dec  = (const float*)d_in[10];
    const float* Wc     = (const float*)d_in[11];
    const float* bc     = (const float*)d_in[12];

    int n = in_sizes[0] / F_IN;       // 50000
    int e = in_sizes[1] / 2;          // 800000
    const int* src = ei;
    const int* dst = ei + e;

    float* out_xrec = (float*)d_out;
    float* out_z    = out_xrec + (size_t)n * F_IN;
    float* out_pred = out_z + (size_t)n * F_L;

    // 1) CSR build
    k_zero<<<(n + 255) / 256, 256>>>(n);
    k_count<<<(e + 255) / 256, 256>>>(dst, e);
    int nb = (n + SCHUNK - 1) / SCHUNK;
    k_scan1<<<nb, SCHUNK>>>(n);
    k_scan2<<<1, 128>>>(nb);
    k_scan3<<<(n + 255) / 256, 256>>>(n, e);
    k_fillcsr<<<(e + 255) / 256, 256>>>(src, dst, e);

    // 2) GEMM1 (HMMA): hpre1h = x @ W_enc  [n,256]x[256,64] -> half
    {
        __half* C;  cudaGetSymbolAddress((void**)&C, g_hpre1h);
        dim3 grid(1, (n + 63) / 64);
        k_gemm_mma<false><<<grid, 128>>>(x, W_enc, C, n, F_IN, F_H);
    }

    // 3) encoder aggregation + relu (warp per node)
    {
        int blocks = (int)(((size_t)n * 32 + 255) / 256);
        k_agg_enc<<<blocks, 256>>>(b_enc, n);
    }

    // 4) fused FCs (z, pred, hd->fp16)
    {
        int blocks = (n + 7) / 8;
        k_fc<<<blocks, 256>>>(Wef, bef, Wdf, bdf, Wc, bc, out_z, out_pred, n);
    }

    // 5) GEMM2 (HMMA): h2h = hdh @ W_dec  [n,64]x[64,256] -> half
    {
        __half *A, *C;
        cudaGetSymbolAddress((void**)&A, g_hdh);
        cudaGetSymbolAddress((void**)&C, g_h2h);
        dim3 grid(F_IN / 64, (n + 63) / 64);
        k_gemm_mma<true><<<grid, 128>>>(A, W_dec, C, n, F_H, F_IN);
    }

    // 6) decoder aggregation -> x_recon (warp per node)
    {
        int blocks = (int)(((size_t)n * 32 + 255) / 256);
        k_agg_dec<<<blocks, 256>>>(b_dec, out_xrec, n);
    }

    (void)n_in; (void)out_size;
}